// round 15
// baseline (speedup 1.0000x reference)
#include <cuda_runtime.h>

#define N_NODES 32768
#define N_EDGES 524288
#define F 128
#define NRBF 32
#define EVD 16
#define NDEG 4
#define RSQRT_D 0.17677669529663687f
#define NPB 32
#define TILE_E 32
#define NTILES (N_EDGES / TILE_E)

// node-phase scratch (device globals: allocation-free)
__device__ float g_q_inv[N_NODES * F];
__device__ float g_k_inv[N_NODES * F];
__device__ float g_v_inv[N_NODES * F];
__device__ float g_q_ev[N_NODES * F];
__device__ float g_k_ev[N_NODES * F];

union F2 { float2 f; unsigned long long u; };
union F4 { float4 v; unsigned long long u[2]; };

__device__ __forceinline__ float silu(float x) { return x / (1.0f + __expf(-x)); }

__device__ __forceinline__ unsigned long long fma2(unsigned long long a,
                                                   unsigned long long b,
                                                   unsigned long long c) {
    unsigned long long d;
    asm("fma.rn.f32x2 %0, %1, %2, %3;" : "=l"(d) : "l"(a), "l"(b), "l"(c));
    return d;
}

__device__ __forceinline__ void red1(float* addr, float a) {
    asm volatile("red.global.add.f32 [%0], %1;" :: "l"(addr), "f"(a) : "memory");
}

__device__ __forceinline__ void red2(float* addr, float a, float b) {
    asm volatile("red.global.add.v2.f32 [%0], {%1,%2};"
                 :: "l"(addr), "f"(a), "f"(b) : "memory");
}

// ---------------------------------------------------------------------------
// Node kernel: q_inv/k_inv/v_inv/q_ev/k_ev = per-head [32x32] projections.
// 256 threads: two 128-thread halves share staged weights (80KB), each
// handles 16 of the 32 nodes per block (4-node register blocking).
// ---------------------------------------------------------------------------
__global__ void node_kernel(const float* __restrict__ x,
                            const float* __restrict__ Wq, const float* __restrict__ Wk,
                            const float* __restrict__ Wv, const float* __restrict__ Wqe,
                            const float* __restrict__ Wke) {
    extern __shared__ float sm[];
    float* w_s = sm;                 // 5 * 4096
    float* x_s = sm + 5 * 4096;      // NPB * 128
    int t = threadIdx.x;

    for (int i = t; i < 4096; i += 256) {
        w_s[i]            = Wq[i];
        w_s[4096 + i]     = Wk[i];
        w_s[2 * 4096 + i] = Wv[i];
        w_s[3 * 4096 + i] = Wqe[i];
        w_s[4 * 4096 + i] = Wke[i];
    }
    int base = blockIdx.x * NPB;
    for (int i = t; i < NPB * F; i += 256) x_s[i] = x[(size_t)base * F + i];
    __syncthreads();

    int tl = t & 127;
    int half = t >> 7;
    int h = tl >> 5, e = tl & 31;
    const float* wq  = w_s + h * 1024 + e;      // stride 32 over d
    const float* wk  = wq + 4096;
    const float* wv  = wq + 2 * 4096;
    const float* wqe = wq + 3 * 4096;
    const float* wke = wq + 4 * 4096;

    for (int n0 = half * 16; n0 < half * 16 + 16; n0 += 4) {
        float aq[4]  = {0, 0, 0, 0}, ak[4]  = {0, 0, 0, 0}, av[4] = {0, 0, 0, 0};
        float aqe[4] = {0, 0, 0, 0}, ake[4] = {0, 0, 0, 0};
#pragma unroll 8
        for (int d = 0; d < 32; d++) {
            float q  = wq[d * 32];
            float k  = wk[d * 32];
            float v  = wv[d * 32];
            float qe = wqe[d * 32];
            float ke = wke[d * 32];
#pragma unroll
            for (int n = 0; n < 4; n++) {
                float xv = x_s[(n0 + n) * F + h * 32 + d];  // warp-broadcast
                aq[n]  = fmaf(xv, q,  aq[n]);
                ak[n]  = fmaf(xv, k,  ak[n]);
                av[n]  = fmaf(xv, v,  av[n]);
                aqe[n] = fmaf(xv, qe, aqe[n]);
                ake[n] = fmaf(xv, ke, ake[n]);
            }
        }
#pragma unroll
        for (int n = 0; n < 4; n++) {
            size_t node = base + n0 + n;
            g_q_inv[node * F + tl] = silu(aq[n]);
            g_k_inv[node * F + tl] = silu(ak[n]);
            g_v_inv[node * F + tl] = av[n];
            g_q_ev[node * F + tl]  = silu(aqe[n]);
            g_k_ev[node * F + tl]  = silu(ake[n]);
        }
    }
}

// ---------------------------------------------------------------------------
// Edge kernel: 256 threads = 8 warps, tile of 32 sequential edges.
// Thread t owns column f=t&127 of Wf_inv (warps 0-3) or Wf_ev (warps 4-7),
// weights as 18 packed f32x2 registers (zero-MOV operands via F4 union).
// q/k gathers software-pipelined across 4-edge groups; v as float2 (l<16)
// with red.v2 scatter; ev sh loads at group start with red1 on l<=2h lanes.
// ---------------------------------------------------------------------------
__global__ void __launch_bounds__(256, 3)
edge_kernel(const float* __restrict__ ev,
            const float* __restrict__ rbf,
            const float* __restrict__ sh,
            const float* __restrict__ cutoffs,
            const float* __restrict__ Wf_inv, const float* __restrict__ bf_inv,
            const float* __restrict__ Wf_ev,  const float* __restrict__ bf_ev,
            const int* __restrict__ senders,
            const int* __restrict__ receivers,
            float* __restrict__ out_inv,   // [N,128]
            float* __restrict__ out_ev)    // [N,16]
{
    __shared__ float feat_s[TILE_E][40];   // 36 used, pad keeps float4 align
    __shared__ float sq_s[TILE_E][16];
    __shared__ int   snd_s[TILE_E], rcv_s[TILE_E];
    __shared__ float sc_s[TILE_E];         // RSQRT_D * cutoff

    int t = threadIdx.x;
    int w = t >> 5, l = t & 31;
    bool is_inv = (w < 4);
    int h = w & 3;
    int f = t & 127;
    int col = h * 32 + l;
    int hh = h * h;        // ev degree-block offset
    int nl = 2 * h;        // ev degree-block last lane

    const float* Wf = is_inv ? Wf_inv : Wf_ev;
    unsigned long long wcol2[18];
#pragma unroll
    for (int j = 0; j < 18; j++) {
        F2 tmp;
        tmp.f = make_float2(Wf[(2 * j) * F + f], Wf[(2 * j + 1) * F + f]);
        wcol2[j] = tmp.u;
    }
    F2 binit; binit.f = make_float2((is_inv ? bf_inv : bf_ev)[f], 0.f);
    const float* gq = is_inv ? g_q_inv : g_q_ev;
    const float* gk = is_inv ? g_k_inv : g_k_ev;

    for (int tile = blockIdx.x; tile < NTILES; tile += gridDim.x) {
        int e0 = tile * TILE_E;

        // A1: ev differences + per-edge scalars (2 items/thread)
#pragma unroll
        for (int i = 0; i < 2; i++) {
            int idx = t + i * 256;
            int e = idx >> 4, j = idx & 15;
            int ss = senders[e0 + e], rr = receivers[e0 + e];
            float d = ev[ss * EVD + j] - ev[rr * EVD + j];
            sq_s[e][j] = d * d;
            if (j == 0) {
                snd_s[e] = ss; rcv_s[e] = rr;
                sc_s[e] = RSQRT_D * cutoffs[e0 + e];
            }
        }
        // A2: rbf -> feat[0:32] (4 items/thread, coalesced)
#pragma unroll
        for (int i = 0; i < 4; i++) {
            int idx = t + i * 256;
            feat_s[idx >> 5][idx & 31] = rbf[(size_t)e0 * NRBF + idx];
        }
        __syncthreads();
        // A3: per-degree invariants -> feat[32:36]
        if (t < TILE_E * NDEG) {
            int e = t >> 2, dg = t & 3;
            int off = dg * dg;
            float s = 0.f;
            for (int i = 0; i <= 2 * dg; i++) s += sq_s[e][off + i];
            feat_s[e][NRBF + dg] = s;
        }
        __syncthreads();

        // B: software-pipelined 4-edge groups (q/k pipelined across groups)
        float qc[4], kc[4];
#pragma unroll
        for (int u = 0; u < 4; u++) {
            qc[u] = gq[rcv_s[u] * F + col];
            kc[u] = gk[snd_s[u] * F + col];
        }

        for (int g = 0; g < TILE_E; g += 4) {
            float qn[4], kn[4];
            if (g + 4 < TILE_E) {
#pragma unroll
                for (int u = 0; u < 4; u++) {
                    int ee = g + 4 + u;
                    qn[u] = gq[rcv_s[ee] * F + col];
                    kn[u] = gk[snd_s[ee] * F + col];
                }
            }
            // v loads for CURRENT group — consumed after GEMV+butterfly
            float2 v2[4];
            float sv[4];
            if (is_inv) {
                if (l < 16) {
#pragma unroll
                    for (int u = 0; u < 4; u++)
                        v2[u] = *(const float2*)(g_v_inv +
                                 (size_t)snd_s[g + u] * F + h * 32 + l * 2);
                }
            } else {
#pragma unroll
                for (int u = 0; u < 4; u++)
                    sv[u] = (l <= nl) ? sh[(size_t)(e0 + g + u) * EVD + hh + l] : 0.f;
            }
            float p[4];
#pragma unroll
            for (int u = 0; u < 4; u++) {
                const float4* fv4 = (const float4*)(&feat_s[g + u][0]);
                unsigned long long a0 = binit.u, a1 = 0ull;
#pragma unroll
                for (int jq = 0; jq < 9; jq++) {
                    F4 fv;
                    fv.v = fv4[jq];
                    a0 = fma2(fv.u[0], wcol2[2 * jq], a0);
                    a1 = fma2(fv.u[1], wcol2[2 * jq + 1], a1);
                }
                F2 r0, r1;
                r0.u = a0; r1.u = a1;
                float fw = (r0.f.x + r1.f.x) + (r0.f.y + r1.f.y);
                p[u] = qc[u] * kc[u] * fw;
            }
#pragma unroll
            for (int o = 16; o > 0; o >>= 1) {
#pragma unroll
                for (int u = 0; u < 4; u++)
                    p[u] += __shfl_xor_sync(0xffffffffu, p[u], o);
            }
            if (is_inv) {
                if (l < 16) {
#pragma unroll
                    for (int u = 0; u < 4; u++) {
                        float m = p[u] * sc_s[g + u];
                        red2(out_inv + (size_t)rcv_s[g + u] * F + h * 32 + l * 2,
                             m * v2[u].x, m * v2[u].y);
                    }
                }
            } else {
                if (l <= nl) {
#pragma unroll
                    for (int u = 0; u < 4; u++)
                        red1(out_ev + (size_t)rcv_s[g + u] * EVD + hh + l,
                             p[u] * sc_s[g + u] * sv[u]);
                }
            }
#pragma unroll
            for (int u = 0; u < 4; u++) { qc[u] = qn[u]; kc[u] = kn[u]; }
        }
        __syncthreads();
    }
}

// ---------------------------------------------------------------------------
extern "C" void kernel_launch(void* const* d_in, const int* in_sizes, int n_in,
                              void* d_out, int out_size) {
    const float* inv_features = (const float*)d_in[0];
    const float* ev_features  = (const float*)d_in[1];
    const float* rbf          = (const float*)d_in[2];
    const float* sh           = (const float*)d_in[3];
    const float* cutoffs      = (const float*)d_in[4];
    const float* W_q_inv      = (const float*)d_in[5];
    const float* W_k_inv      = (const float*)d_in[6];
    const float* W_v_inv      = (const float*)d_in[7];
    const float* W_q_ev       = (const float*)d_in[8];
    const float* W_k_ev       = (const float*)d_in[9];
    const float* Wf_inv       = (const float*)d_in[10];
    const float* bf_inv       = (const float*)d_in[11];
    const float* Wf_ev        = (const float*)d_in[12];
    const float* bf_ev        = (const float*)d_in[13];
    const int*   senders      = (const int*)d_in[14];
    const int*   receivers    = (const int*)d_in[15];

    float* out     = (float*)d_out;
    float* out_inv = out;                               // [N,128]
    float* out_ev  = out + (size_t)N_NODES * F;         // [N,16]

    cudaMemsetAsync(d_out, 0, (size_t)out_size * sizeof(float));

    size_t smem = (5 * 4096 + NPB * F) * sizeof(float); // 96 KB
    cudaFuncSetAttribute(node_kernel, cudaFuncAttributeMaxDynamicSharedMemorySize, (int)smem);
    node_kernel<<<N_NODES / NPB, 256, smem>>>(inv_features, W_q_inv, W_k_inv, W_v_inv,
                                              W_q_ev, W_k_ev);
    edge_kernel<<<2048, 256>>>(ev_features, rbf, sh, cutoffs,
                               Wf_inv, bf_inv, Wf_ev, bf_ev,
                               senders, receivers, out_inv, out_ev);
}

// round 16
// speedup vs baseline: 1.0084x; 1.0084x over previous
#include <cuda_runtime.h>

#define N_NODES 32768
#define N_EDGES 524288
#define F 128
#define NRBF 32
#define EVD 16
#define NDEG 4
#define RSQRT_D 0.17677669529663687f
#define NPB 32
#define TILE_E 32
#define NTILES (N_EDGES / TILE_E)

// node-phase scratch (device globals: allocation-free)
__device__ float g_q_inv[N_NODES * F];
__device__ float g_k_inv[N_NODES * F];
__device__ float g_v_inv[N_NODES * F];
__device__ float g_q_ev[N_NODES * F];
__device__ float g_k_ev[N_NODES * F];

union F2 { float2 f; unsigned long long u; };
union F4 { float4 v; unsigned long long u[2]; };

__device__ __forceinline__ float silu(float x) { return x / (1.0f + __expf(-x)); }

__device__ __forceinline__ unsigned long long fma2(unsigned long long a,
                                                   unsigned long long b,
                                                   unsigned long long c) {
    unsigned long long d;
    asm("fma.rn.f32x2 %0, %1, %2, %3;" : "=l"(d) : "l"(a), "l"(b), "l"(c));
    return d;
}

__device__ __forceinline__ void red1(float* addr, float a) {
    asm volatile("red.global.add.f32 [%0], %1;" :: "l"(addr), "f"(a) : "memory");
}

__device__ __forceinline__ void red2(float* addr, float a, float b) {
    asm volatile("red.global.add.v2.f32 [%0], {%1,%2};"
                 :: "l"(addr), "f"(a), "f"(b) : "memory");
}

// ---------------------------------------------------------------------------
// Node kernel: q_inv/k_inv/v_inv/q_ev/k_ev = per-head [32x32] projections.
// 256 threads: two 128-thread halves share staged weights (80KB), each
// handles 16 of the 32 nodes per block (4-node register blocking).
// ---------------------------------------------------------------------------
__global__ void node_kernel(const float* __restrict__ x,
                            const float* __restrict__ Wq, const float* __restrict__ Wk,
                            const float* __restrict__ Wv, const float* __restrict__ Wqe,
                            const float* __restrict__ Wke) {
    extern __shared__ float sm[];
    float* w_s = sm;                 // 5 * 4096
    float* x_s = sm + 5 * 4096;      // NPB * 128
    int t = threadIdx.x;

    for (int i = t; i < 4096; i += 256) {
        w_s[i]            = Wq[i];
        w_s[4096 + i]     = Wk[i];
        w_s[2 * 4096 + i] = Wv[i];
        w_s[3 * 4096 + i] = Wqe[i];
        w_s[4 * 4096 + i] = Wke[i];
    }
    int base = blockIdx.x * NPB;
    for (int i = t; i < NPB * F; i += 256) x_s[i] = x[(size_t)base * F + i];
    __syncthreads();

    int tl = t & 127;
    int half = t >> 7;
    int h = tl >> 5, e = tl & 31;
    const float* wq  = w_s + h * 1024 + e;      // stride 32 over d
    const float* wk  = wq + 4096;
    const float* wv  = wq + 2 * 4096;
    const float* wqe = wq + 3 * 4096;
    const float* wke = wq + 4 * 4096;

    for (int n0 = half * 16; n0 < half * 16 + 16; n0 += 4) {
        float aq[4]  = {0, 0, 0, 0}, ak[4]  = {0, 0, 0, 0}, av[4] = {0, 0, 0, 0};
        float aqe[4] = {0, 0, 0, 0}, ake[4] = {0, 0, 0, 0};
#pragma unroll 8
        for (int d = 0; d < 32; d++) {
            float q  = wq[d * 32];
            float k  = wk[d * 32];
            float v  = wv[d * 32];
            float qe = wqe[d * 32];
            float ke = wke[d * 32];
#pragma unroll
            for (int n = 0; n < 4; n++) {
                float xv = x_s[(n0 + n) * F + h * 32 + d];  // warp-broadcast
                aq[n]  = fmaf(xv, q,  aq[n]);
                ak[n]  = fmaf(xv, k,  ak[n]);
                av[n]  = fmaf(xv, v,  av[n]);
                aqe[n] = fmaf(xv, qe, aqe[n]);
                ake[n] = fmaf(xv, ke, ake[n]);
            }
        }
#pragma unroll
        for (int n = 0; n < 4; n++) {
            size_t node = base + n0 + n;
            g_q_inv[node * F + tl] = silu(aq[n]);
            g_k_inv[node * F + tl] = silu(ak[n]);
            g_v_inv[node * F + tl] = av[n];
            g_q_ev[node * F + tl]  = silu(aqe[n]);
            g_k_ev[node * F + tl]  = silu(ake[n]);
        }
    }
}

// ---------------------------------------------------------------------------
// Edge kernel: 256 threads = 8 warps, tile of 32 sequential edges.
// Thread t owns column f=t&127 of Wf_inv (warps 0-3) or Wf_ev (warps 4-7),
// weights as 18 packed f32x2 registers (zero-MOV operands via F4 union).
// q/k gathers software-pipelined across 4-edge groups; v as float2 (l<16)
// with red.v2 scatter; ev sh loads at group start with red1 on l<=2h lanes.
// ---------------------------------------------------------------------------
__global__ void __launch_bounds__(256, 3)
edge_kernel(const float* __restrict__ ev,
            const float* __restrict__ rbf,
            const float* __restrict__ sh,
            const float* __restrict__ cutoffs,
            const float* __restrict__ Wf_inv, const float* __restrict__ bf_inv,
            const float* __restrict__ Wf_ev,  const float* __restrict__ bf_ev,
            const int* __restrict__ senders,
            const int* __restrict__ receivers,
            float* __restrict__ out_inv,   // [N,128]
            float* __restrict__ out_ev)    // [N,16]
{
    __shared__ float feat_s[TILE_E][40];   // 36 used, pad keeps float4 align
    __shared__ float sq_s[TILE_E][16];
    __shared__ int   snd_s[TILE_E], rcv_s[TILE_E];
    __shared__ float sc_s[TILE_E];         // RSQRT_D * cutoff

    int t = threadIdx.x;
    int w = t >> 5, l = t & 31;
    bool is_inv = (w < 4);
    int h = w & 3;
    int f = t & 127;
    int col = h * 32 + l;
    int hh = h * h;        // ev degree-block offset
    int nl = 2 * h;        // ev degree-block last lane

    const float* Wf = is_inv ? Wf_inv : Wf_ev;
    unsigned long long wcol2[18];
#pragma unroll
    for (int j = 0; j < 18; j++) {
        F2 tmp;
        tmp.f = make_float2(Wf[(2 * j) * F + f], Wf[(2 * j + 1) * F + f]);
        wcol2[j] = tmp.u;
    }
    F2 binit; binit.f = make_float2((is_inv ? bf_inv : bf_ev)[f], 0.f);
    const float* gq = is_inv ? g_q_inv : g_q_ev;
    const float* gk = is_inv ? g_k_inv : g_k_ev;

    for (int tile = blockIdx.x; tile < NTILES; tile += gridDim.x) {
        int e0 = tile * TILE_E;

        // A1: ev differences + per-edge scalars (2 items/thread)
#pragma unroll
        for (int i = 0; i < 2; i++) {
            int idx = t + i * 256;
            int e = idx >> 4, j = idx & 15;
            int ss = senders[e0 + e], rr = receivers[e0 + e];
            float d = ev[ss * EVD + j] - ev[rr * EVD + j];
            sq_s[e][j] = d * d;
            if (j == 0) {
                snd_s[e] = ss; rcv_s[e] = rr;
                sc_s[e] = RSQRT_D * cutoffs[e0 + e];
            }
        }
        // A2: rbf -> feat[0:32] (4 items/thread, coalesced)
#pragma unroll
        for (int i = 0; i < 4; i++) {
            int idx = t + i * 256;
            feat_s[idx >> 5][idx & 31] = rbf[(size_t)e0 * NRBF + idx];
        }
        __syncthreads();
        // A3: per-degree invariants -> feat[32:36]
        if (t < TILE_E * NDEG) {
            int e = t >> 2, dg = t & 3;
            int off = dg * dg;
            float s = 0.f;
            for (int i = 0; i <= 2 * dg; i++) s += sq_s[e][off + i];
            feat_s[e][NRBF + dg] = s;
        }
        __syncthreads();

        // B: software-pipelined 4-edge groups (q/k pipelined across groups)
        float qc[4], kc[4];
#pragma unroll
        for (int u = 0; u < 4; u++) {
            qc[u] = gq[rcv_s[u] * F + col];
            kc[u] = gk[snd_s[u] * F + col];
        }

        for (int g = 0; g < TILE_E; g += 4) {
            float qn[4], kn[4];
            if (g + 4 < TILE_E) {
#pragma unroll
                for (int u = 0; u < 4; u++) {
                    int ee = g + 4 + u;
                    qn[u] = gq[rcv_s[ee] * F + col];
                    kn[u] = gk[snd_s[ee] * F + col];
                }
            }
            // v loads for CURRENT group — consumed after GEMV+butterfly
            float2 v2[4];
            float sv[4];
            if (is_inv) {
                if (l < 16) {
#pragma unroll
                    for (int u = 0; u < 4; u++)
                        v2[u] = *(const float2*)(g_v_inv +
                                 (size_t)snd_s[g + u] * F + h * 32 + l * 2);
                }
            } else {
#pragma unroll
                for (int u = 0; u < 4; u++)
                    sv[u] = (l <= nl) ? sh[(size_t)(e0 + g + u) * EVD + hh + l] : 0.f;
            }
            float p[4];
#pragma unroll
            for (int u = 0; u < 4; u++) {
                const float4* fv4 = (const float4*)(&feat_s[g + u][0]);
                unsigned long long a0 = binit.u, a1 = 0ull;
#pragma unroll
                for (int jq = 0; jq < 9; jq++) {
                    F4 fv;
                    fv.v = fv4[jq];
                    a0 = fma2(fv.u[0], wcol2[2 * jq], a0);
                    a1 = fma2(fv.u[1], wcol2[2 * jq + 1], a1);
                }
                F2 r0, r1;
                r0.u = a0; r1.u = a1;
                float fw = (r0.f.x + r1.f.x) + (r0.f.y + r1.f.y);
                p[u] = qc[u] * kc[u] * fw;
            }
#pragma unroll
            for (int o = 16; o > 0; o >>= 1) {
#pragma unroll
                for (int u = 0; u < 4; u++)
                    p[u] += __shfl_xor_sync(0xffffffffu, p[u], o);
            }
            if (is_inv) {
                if (l < 16) {
#pragma unroll
                    for (int u = 0; u < 4; u++) {
                        float m = p[u] * sc_s[g + u];
                        red2(out_inv + (size_t)rcv_s[g + u] * F + h * 32 + l * 2,
                             m * v2[u].x, m * v2[u].y);
                    }
                }
            } else {
                if (l <= nl) {
#pragma unroll
                    for (int u = 0; u < 4; u++)
                        red1(out_ev + (size_t)rcv_s[g + u] * EVD + hh + l,
                             p[u] * sc_s[g + u] * sv[u]);
                }
            }
#pragma unroll
            for (int u = 0; u < 4; u++) { qc[u] = qn[u]; kc[u] = kn[u]; }
        }
        __syncthreads();
    }
}

// ---------------------------------------------------------------------------
extern "C" void kernel_launch(void* const* d_in, const int* in_sizes, int n_in,
                              void* d_out, int out_size) {
    const float* inv_features = (const float*)d_in[0];
    const float* ev_features  = (const float*)d_in[1];
    const float* rbf          = (const float*)d_in[2];
    const float* sh           = (const float*)d_in[3];
    const float* cutoffs      = (const float*)d_in[4];
    const float* W_q_inv      = (const float*)d_in[5];
    const float* W_k_inv      = (const float*)d_in[6];
    const float* W_v_inv      = (const float*)d_in[7];
    const float* W_q_ev       = (const float*)d_in[8];
    const float* W_k_ev       = (const float*)d_in[9];
    const float* Wf_inv       = (const float*)d_in[10];
    const float* bf_inv       = (const float*)d_in[11];
    const float* Wf_ev        = (const float*)d_in[12];
    const float* bf_ev        = (const float*)d_in[13];
    const int*   senders      = (const int*)d_in[14];
    const int*   receivers    = (const int*)d_in[15];

    float* out     = (float*)d_out;
    float* out_inv = out;                               // [N,128]
    float* out_ev  = out + (size_t)N_NODES * F;         // [N,16]

    cudaMemsetAsync(d_out, 0, (size_t)out_size * sizeof(float));

    size_t smem = (5 * 4096 + NPB * F) * sizeof(float); // 96 KB
    cudaFuncSetAttribute(node_kernel, cudaFuncAttributeMaxDynamicSharedMemorySize, (int)smem);
    node_kernel<<<N_NODES / NPB, 256, smem>>>(inv_features, W_q_inv, W_k_inv, W_v_inv,
                                              W_q_ev, W_k_ev);
    edge_kernel<<<2048, 256>>>(ev_features, rbf, sh, cutoffs,
                               Wf_inv, bf_inv, Wf_ev, bf_ev,
                               senders, receivers, out_inv, out_ev);
}

// round 17
// speedup vs baseline: 1.0094x; 1.0011x over previous
#include <cuda_runtime.h>

#define N_NODES 32768
#define N_EDGES 524288
#define F 128
#define NRBF 32
#define EVD 16
#define NDEG 4
#define RSQRT_D 0.17677669529663687f
#define NPB 32
#define TILE_E 32
#define NTILES (N_EDGES / TILE_E)

// node-phase scratch (device globals: allocation-free)
__device__ float g_q_inv[N_NODES * F];
__device__ float g_k_inv[N_NODES * F];
__device__ float g_v_inv[N_NODES * F];
__device__ float g_q_ev[N_NODES * F];
__device__ float g_k_ev[N_NODES * F];

union F2 { float2 f; unsigned long long u; };
union F4 { float4 v; unsigned long long u[2]; };

__device__ __forceinline__ float silu(float x) { return x / (1.0f + __expf(-x)); }

__device__ __forceinline__ unsigned long long fma2(unsigned long long a,
                                                   unsigned long long b,
                                                   unsigned long long c) {
    unsigned long long d;
    asm("fma.rn.f32x2 %0, %1, %2, %3;" : "=l"(d) : "l"(a), "l"(b), "l"(c));
    return d;
}

__device__ __forceinline__ void red1(float* addr, float a) {
    asm volatile("red.global.add.f32 [%0], %1;" :: "l"(addr), "f"(a) : "memory");
}

__device__ __forceinline__ void red2(float* addr, float a, float b) {
    asm volatile("red.global.add.v2.f32 [%0], {%1,%2};"
                 :: "l"(addr), "f"(a), "f"(b) : "memory");
}

// ---------------------------------------------------------------------------
// Node kernel: q_inv/k_inv/v_inv/q_ev/k_ev = per-head [32x32] projections.
// 256 threads: two 128-thread halves share staged weights (80KB), each
// handles 16 of the 32 nodes per block (4-node register blocking).
// ---------------------------------------------------------------------------
__global__ void node_kernel(const float* __restrict__ x,
                            const float* __restrict__ Wq, const float* __restrict__ Wk,
                            const float* __restrict__ Wv, const float* __restrict__ Wqe,
                            const float* __restrict__ Wke) {
    extern __shared__ float sm[];
    float* w_s = sm;                 // 5 * 4096
    float* x_s = sm + 5 * 4096;      // NPB * 128
    int t = threadIdx.x;

    for (int i = t; i < 4096; i += 256) {
        w_s[i]            = Wq[i];
        w_s[4096 + i]     = Wk[i];
        w_s[2 * 4096 + i] = Wv[i];
        w_s[3 * 4096 + i] = Wqe[i];
        w_s[4 * 4096 + i] = Wke[i];
    }
    int base = blockIdx.x * NPB;
    for (int i = t; i < NPB * F; i += 256) x_s[i] = x[(size_t)base * F + i];
    __syncthreads();

    int tl = t & 127;
    int half = t >> 7;
    int h = tl >> 5, e = tl & 31;
    const float* wq  = w_s + h * 1024 + e;      // stride 32 over d
    const float* wk  = wq + 4096;
    const float* wv  = wq + 2 * 4096;
    const float* wqe = wq + 3 * 4096;
    const float* wke = wq + 4 * 4096;

    for (int n0 = half * 16; n0 < half * 16 + 16; n0 += 4) {
        float aq[4]  = {0, 0, 0, 0}, ak[4]  = {0, 0, 0, 0}, av[4] = {0, 0, 0, 0};
        float aqe[4] = {0, 0, 0, 0}, ake[4] = {0, 0, 0, 0};
#pragma unroll 8
        for (int d = 0; d < 32; d++) {
            float q  = wq[d * 32];
            float k  = wk[d * 32];
            float v  = wv[d * 32];
            float qe = wqe[d * 32];
            float ke = wke[d * 32];
#pragma unroll
            for (int n = 0; n < 4; n++) {
                float xv = x_s[(n0 + n) * F + h * 32 + d];  // warp-broadcast
                aq[n]  = fmaf(xv, q,  aq[n]);
                ak[n]  = fmaf(xv, k,  ak[n]);
                av[n]  = fmaf(xv, v,  av[n]);
                aqe[n] = fmaf(xv, qe, aqe[n]);
                ake[n] = fmaf(xv, ke, ake[n]);
            }
        }
#pragma unroll
        for (int n = 0; n < 4; n++) {
            size_t node = base + n0 + n;
            g_q_inv[node * F + tl] = silu(aq[n]);
            g_k_inv[node * F + tl] = silu(ak[n]);
            g_v_inv[node * F + tl] = av[n];
            g_q_ev[node * F + tl]  = silu(aqe[n]);
            g_k_ev[node * F + tl]  = silu(ake[n]);
        }
    }
}

// ---------------------------------------------------------------------------
// Edge kernel: 256 threads = 8 warps, tile of 32 sequential edges.
// Thread t owns column f=t&127 of Wf_inv (warps 0-3) or Wf_ev (warps 4-7),
// weights as 18 packed f32x2 registers (zero-MOV operands via F4 union).
// q/k gathers software-pipelined across 4-edge groups; v as float2 (l<16)
// with red.v2 scatter; ev sh loads at group start with red1 on l<=2h lanes.
// ---------------------------------------------------------------------------
__global__ void __launch_bounds__(256, 3)
edge_kernel(const float* __restrict__ ev,
            const float* __restrict__ rbf,
            const float* __restrict__ sh,
            const float* __restrict__ cutoffs,
            const float* __restrict__ Wf_inv, const float* __restrict__ bf_inv,
            const float* __restrict__ Wf_ev,  const float* __restrict__ bf_ev,
            const int* __restrict__ senders,
            const int* __restrict__ receivers,
            float* __restrict__ out_inv,   // [N,128]
            float* __restrict__ out_ev)    // [N,16]
{
    __shared__ float feat_s[TILE_E][40];   // 36 used, pad keeps float4 align
    __shared__ float sq_s[TILE_E][16];
    __shared__ int   snd_s[TILE_E], rcv_s[TILE_E];
    __shared__ float sc_s[TILE_E];         // RSQRT_D * cutoff

    int t = threadIdx.x;
    int w = t >> 5, l = t & 31;
    bool is_inv = (w < 4);
    int h = w & 3;
    int f = t & 127;
    int col = h * 32 + l;
    int hh = h * h;        // ev degree-block offset
    int nl = 2 * h;        // ev degree-block last lane

    const float* Wf = is_inv ? Wf_inv : Wf_ev;
    unsigned long long wcol2[18];
#pragma unroll
    for (int j = 0; j < 18; j++) {
        F2 tmp;
        tmp.f = make_float2(Wf[(2 * j) * F + f], Wf[(2 * j + 1) * F + f]);
        wcol2[j] = tmp.u;
    }
    F2 binit; binit.f = make_float2((is_inv ? bf_inv : bf_ev)[f], 0.f);
    const float* gq = is_inv ? g_q_inv : g_q_ev;
    const float* gk = is_inv ? g_k_inv : g_k_ev;

    for (int tile = blockIdx.x; tile < NTILES; tile += gridDim.x) {
        int e0 = tile * TILE_E;

        // A1: ev differences + per-edge scalars (2 items/thread)
#pragma unroll
        for (int i = 0; i < 2; i++) {
            int idx = t + i * 256;
            int e = idx >> 4, j = idx & 15;
            int ss = senders[e0 + e], rr = receivers[e0 + e];
            float d = ev[ss * EVD + j] - ev[rr * EVD + j];
            sq_s[e][j] = d * d;
            if (j == 0) {
                snd_s[e] = ss; rcv_s[e] = rr;
                sc_s[e] = RSQRT_D * cutoffs[e0 + e];
            }
        }
        // A2: rbf -> feat[0:32] (4 items/thread, coalesced)
#pragma unroll
        for (int i = 0; i < 4; i++) {
            int idx = t + i * 256;
            feat_s[idx >> 5][idx & 31] = rbf[(size_t)e0 * NRBF + idx];
        }
        __syncthreads();
        // A3: per-degree invariants -> feat[32:36]
        if (t < TILE_E * NDEG) {
            int e = t >> 2, dg = t & 3;
            int off = dg * dg;
            float s = 0.f;
            for (int i = 0; i <= 2 * dg; i++) s += sq_s[e][off + i];
            feat_s[e][NRBF + dg] = s;
        }
        __syncthreads();

        // B: software-pipelined 4-edge groups (q/k pipelined across groups)
        float qc[4], kc[4];
#pragma unroll
        for (int u = 0; u < 4; u++) {
            qc[u] = gq[rcv_s[u] * F + col];
            kc[u] = gk[snd_s[u] * F + col];
        }

        for (int g = 0; g < TILE_E; g += 4) {
            float qn[4], kn[4];
            if (g + 4 < TILE_E) {
#pragma unroll
                for (int u = 0; u < 4; u++) {
                    int ee = g + 4 + u;
                    qn[u] = gq[rcv_s[ee] * F + col];
                    kn[u] = gk[snd_s[ee] * F + col];
                }
            }
            // v loads for CURRENT group — consumed after GEMV+butterfly
            float2 v2[4];
            float sv[4];
            if (is_inv) {
                if (l < 16) {
#pragma unroll
                    for (int u = 0; u < 4; u++)
                        v2[u] = *(const float2*)(g_v_inv +
                                 (size_t)snd_s[g + u] * F + h * 32 + l * 2);
                }
            } else {
#pragma unroll
                for (int u = 0; u < 4; u++)
                    sv[u] = (l <= nl) ? sh[(size_t)(e0 + g + u) * EVD + hh + l] : 0.f;
            }
            float p[4];
#pragma unroll
            for (int u = 0; u < 4; u++) {
                const float4* fv4 = (const float4*)(&feat_s[g + u][0]);
                unsigned long long a0 = binit.u, a1 = 0ull;
#pragma unroll
                for (int jq = 0; jq < 9; jq++) {
                    F4 fv;
                    fv.v = fv4[jq];
                    a0 = fma2(fv.u[0], wcol2[2 * jq], a0);
                    a1 = fma2(fv.u[1], wcol2[2 * jq + 1], a1);
                }
                F2 r0, r1;
                r0.u = a0; r1.u = a1;
                float fw = (r0.f.x + r1.f.x) + (r0.f.y + r1.f.y);
                p[u] = qc[u] * kc[u] * fw;
            }
#pragma unroll
            for (int o = 16; o > 0; o >>= 1) {
#pragma unroll
                for (int u = 0; u < 4; u++)
                    p[u] += __shfl_xor_sync(0xffffffffu, p[u], o);
            }
            if (is_inv) {
                if (l < 16) {
#pragma unroll
                    for (int u = 0; u < 4; u++) {
                        float m = p[u] * sc_s[g + u];
                        red2(out_inv + (size_t)rcv_s[g + u] * F + h * 32 + l * 2,
                             m * v2[u].x, m * v2[u].y);
                    }
                }
            } else {
                if (l <= nl) {
#pragma unroll
                    for (int u = 0; u < 4; u++)
                        red1(out_ev + (size_t)rcv_s[g + u] * EVD + hh + l,
                             p[u] * sc_s[g + u] * sv[u]);
                }
            }
#pragma unroll
            for (int u = 0; u < 4; u++) { qc[u] = qn[u]; kc[u] = kn[u]; }
        }
        __syncthreads();
    }
}

// ---------------------------------------------------------------------------
extern "C" void kernel_launch(void* const* d_in, const int* in_sizes, int n_in,
                              void* d_out, int out_size) {
    const float* inv_features = (const float*)d_in[0];
    const float* ev_features  = (const float*)d_in[1];
    const float* rbf          = (const float*)d_in[2];
    const float* sh           = (const float*)d_in[3];
    const float* cutoffs      = (const float*)d_in[4];
    const float* W_q_inv      = (const float*)d_in[5];
    const float* W_k_inv      = (const float*)d_in[6];
    const float* W_v_inv      = (const float*)d_in[7];
    const float* W_q_ev       = (const float*)d_in[8];
    const float* W_k_ev       = (const float*)d_in[9];
    const float* Wf_inv       = (const float*)d_in[10];
    const float* bf_inv       = (const float*)d_in[11];
    const float* Wf_ev        = (const float*)d_in[12];
    const float* bf_ev        = (const float*)d_in[13];
    const int*   senders      = (const int*)d_in[14];
    const int*   receivers    = (const int*)d_in[15];

    float* out     = (float*)d_out;
    float* out_inv = out;                               // [N,128]
    float* out_ev  = out + (size_t)N_NODES * F;         // [N,16]

    cudaMemsetAsync(d_out, 0, (size_t)out_size * sizeof(float));

    size_t smem = (5 * 4096 + NPB * F) * sizeof(float); // 96 KB
    cudaFuncSetAttribute(node_kernel, cudaFuncAttributeMaxDynamicSharedMemorySize, (int)smem);
    node_kernel<<<N_NODES / NPB, 256, smem>>>(inv_features, W_q_inv, W_k_inv, W_v_inv,
                                              W_q_ev, W_k_ev);
    edge_kernel<<<2048, 256>>>(ev_features, rbf, sh, cutoffs,
                               Wf_inv, bf_inv, Wf_ev, bf_ev,
                               senders, receivers, out_inv, out_ev);
}